// round 12
// baseline (speedup 1.0000x reference)
#include <cuda_runtime.h>
#include <math.h>

#define BB 8
#define CC 256
#define HH 56
#define WW 56
#define HW (HH*WW)          // 3136
#define KK 3
#define TAPS 9
#define MID 51
#define CKK (CC*TAPS)       // 2304
#define GAIN_OVER_K 0.4714045207910317f   // sqrt(2)/3

__device__ __align__(16) float g_pooled[BB * CC];
__device__ __align__(16) float g_sf[BB * TAPS * HW];
__device__ __align__(16) float g_cf[BB * CKK];

typedef unsigned long long ull;

// ---- f32x2 packed helpers (sm_103a) --------------------------------------
__device__ __forceinline__ ull pack2(float x, float y) {
    ull r; asm("mov.b64 %0, {%1, %2};" : "=l"(r) : "f"(x), "f"(y)); return r;
}
__device__ __forceinline__ void unpack2(ull v, float& x, float& y) {
    asm("mov.b64 {%0, %1}, %2;" : "=f"(x), "=f"(y) : "l"(v));
}
__device__ __forceinline__ ull mul2(ull a, ull b) {
    ull d; asm("mul.rn.f32x2 %0, %1, %2;" : "=l"(d) : "l"(a), "l"(b)); return d;
}
__device__ __forceinline__ ull fma2(ull a, ull b, ull c) {
    ull d; asm("fma.rn.f32x2 %0, %1, %2, %3;" : "=l"(d) : "l"(a), "l"(b), "l"(c)); return d;
}
__device__ __forceinline__ unsigned smem_u32(const void* p) {
    unsigned a;
    asm("{ .reg .u64 t; cvta.to.shared.u64 t, %1; cvt.u32.u64 %0, t; }"
        : "=r"(a) : "l"(p));
    return a;
}
__device__ __forceinline__ void cp_async16(unsigned dst, const void* src) {
    asm volatile("cp.async.cg.shared.global [%0], [%1], 16;"
                 :: "r"(dst), "l"(src) : "memory");
}

// ---------------------------------------------------------------------------
// Kernel A: bx < 98 -> sf for a 32-px tile, x staged to smem via cp.async.
//           bx >= 98 -> pooled means (warp per channel).
// Block 512 thr, 44 KB smem, 32 regs -> 4 CTAs/SM, 64 warps/SM.
// ---------------------------------------------------------------------------
__global__ void __launch_bounds__(512, 4) kA_sf_pool(
    const float* __restrict__ x,
    const float* __restrict__ ws,
    const float* __restrict__ bs)
{
    __shared__ float ws_s[CC * 12];           // 12 KB
    __shared__ __align__(16) float xs[CC * 32];  // 32 KB; aliased as red later

    const int b    = blockIdx.y;
    const int bx   = blockIdx.x;
    const int tid  = threadIdx.x;
    const int lane = tid & 31;
    const int w    = tid >> 5;

    if (bx >= 98) {
        const int c = (bx - 98) * 16 + w;
        const float4* p4 = (const float4*)(x + ((size_t)b * CC + c) * HW);
        float s = 0.f;
        for (int j = lane; j < 784; j += 32) {
            float4 v = __ldg(p4 + j);
            s += (v.x + v.y) + (v.z + v.w);
        }
#pragma unroll
        for (int o = 16; o > 0; o >>= 1) s += __shfl_xor_sync(0xffffffffu, s, o);
        if (lane == 0) g_pooled[b * CC + c] = s * (1.f / (float)HW);
        return;
    }

    // ---- stage x[256ch x 32px] via cp.async (4 x 16B per thread) ----
    {
        const float* xsrc = x + (size_t)b * CC * HW + bx * 32;
        const unsigned xs_b = smem_u32(xs);
#pragma unroll
        for (int f = 0; f < 4; f++) {
            int e = tid + f * 512;            // float4 id, 0..2047
            int c = e >> 3;
            int q = e & 7;
            cp_async16(xs_b + e * 16, xsrc + (size_t)c * HW + q * 4);
        }
        asm volatile("cp.async.commit_group;" ::: "memory");
    }

    // ---- stage ws transposed [c][12] (overlaps the async copy) ----
#pragma unroll
    for (int i = tid; i < TAPS * CC; i += 512) {
        int n = i >> 8, c = i & 255;
        ws_s[c * 12 + n] = ws[i];
    }
    asm volatile("cp.async.wait_group 0;" ::: "memory");
    __syncthreads();

    // ---- compute: warp w owns channels [w*16, w*16+16), lane = pixel ----
    float acc[TAPS];
#pragma unroll
    for (int n = 0; n < TAPS; n++) acc[n] = 0.f;

    const float* xrow = xs + (w * 16) * 32 + lane;
#pragma unroll
    for (int cc = 0; cc < 16; cc++) {
        float xv = xrow[cc * 32];
        const float* wr = ws_s + (w * 16 + cc) * 12;
        float4 wa = *(const float4*)(wr);
        float4 wb = *(const float4*)(wr + 4);
        float  w8 = wr[8];
        acc[0] = fmaf(xv, wa.x, acc[0]);
        acc[1] = fmaf(xv, wa.y, acc[1]);
        acc[2] = fmaf(xv, wa.z, acc[2]);
        acc[3] = fmaf(xv, wa.w, acc[3]);
        acc[4] = fmaf(xv, wb.x, acc[4]);
        acc[5] = fmaf(xv, wb.y, acc[5]);
        acc[6] = fmaf(xv, wb.z, acc[6]);
        acc[7] = fmaf(xv, wb.w, acc[7]);
        acc[8] = fmaf(xv, w8,   acc[8]);
    }

    __syncthreads();                 // all xs reads complete
    float* red = xs;                 // alias: 16*9*32 = 4608 <= 8192 floats
#pragma unroll
    for (int n = 0; n < TAPS; n++)
        red[(w * TAPS + n) * 32 + lane] = acc[n];
    __syncthreads();

    if (tid < 32) {
        float a[TAPS];
        float m = 0.f;
#pragma unroll
        for (int n = 0; n < TAPS; n++) {
            float s = 0.f;
#pragma unroll
            for (int gg = 0; gg < 16; gg++) s += red[(gg * TAPS + n) * 32 + tid];
            a[n] = s + __ldg(bs + n);
            m += a[n];
        }
        m *= (1.f / 9.f);
        float ss = 0.f;
#pragma unroll
        for (int n = 0; n < TAPS; n++) { float d = a[n] - m; ss = fmaf(d, d, ss); }
        float inv = GAIN_OVER_K / (sqrtf(ss * (1.f / 8.f)) + 1e-10f);
        const int pix2 = bx * 32 + tid;
#pragma unroll
        for (int n = 0; n < TAPS; n++)
            g_sf[((size_t)b * TAPS + n) * HW + pix2] = (a[n] - m) * inv;
    }
}

// ---------------------------------------------------------------------------
// Kernel 2 (frozen): MLP + per-channel normalize -> cf.
// ---------------------------------------------------------------------------
__global__ void __launch_bounds__(256) k2_mlp_cf(
    const float* __restrict__ w1, const float* __restrict__ b1,
    const float* __restrict__ w2, const float* __restrict__ b2,
    const float* __restrict__ fn_std)
{
    __shared__ float pooled_s[CC];
    __shared__ float y1_s[52];
    __shared__ float w2c[144 * MID];
    __shared__ float y2_s[144];

    const int cg   = blockIdx.x;
    const int b    = blockIdx.y;
    const int tid  = threadIdx.x;
    const int warp = tid >> 5;
    const int lane = tid & 31;

    pooled_s[tid] = g_pooled[b * CC + tid];

    {
        const float4* src = (const float4*)(w2 + (size_t)cg * 144 * MID);
#pragma unroll
        for (int i = tid; i < 144 * MID / 4; i += 256)
            ((float4*)w2c)[i] = __ldg(src + i);
    }
    __syncthreads();

    for (int j = warp; j < MID; j += 8) {
        const float* wr = w1 + j * CC;
        float s = 0.f;
#pragma unroll
        for (int k = 0; k < CC / 32; k++)
            s = fmaf(pooled_s[lane + k * 32], __ldg(wr + lane + k * 32), s);
#pragma unroll
        for (int o = 16; o > 0; o >>= 1) s += __shfl_xor_sync(0xffffffffu, s, o);
        if (lane == 0) y1_s[j] = fmaxf(s + __ldg(b1 + j), 0.f);
    }
    __syncthreads();

    if (tid < 144) {
        const int r = cg * 144 + tid;
        float a = __ldg(b2 + r);
        const float* row = w2c + tid * MID;
#pragma unroll
        for (int m = 0; m < MID; m++) a = fmaf(y1_s[m], row[m], a);
        y2_s[tid] = a;
    }
    __syncthreads();

    if (tid < 16) {
        const int c = cg * 16 + tid;
        float y[TAPS];
        float m = 0.f;
#pragma unroll
        for (int k = 0; k < TAPS; k++) { y[k] = y2_s[tid * TAPS + k]; m += y[k]; }
        m *= (1.f / 9.f);
        float ss = 0.f;
#pragma unroll
        for (int k = 0; k < TAPS; k++) { float d = y[k] - m; ss = fmaf(d, d, ss); }
        float inv = 1.f / (sqrtf(ss * (1.f / 8.f)) + 1e-10f);
#pragma unroll
        for (int k = 0; k < TAPS; k++)
            g_cf[(size_t)b * CKK + c * TAPS + k] =
                (y[k] - m) * inv * __ldg(fn_std + c * TAPS + k);
    }
}

// ---------------------------------------------------------------------------
// Kernel 3 (frozen, R11): DDF combine, bulk-copy halos, f32x2 math.
// ---------------------------------------------------------------------------
#define K3_CG 16
#define HSTR 56
#define HSZ  (10 * HSTR)     // 560
__global__ void __launch_bounds__(224) k3_ddf(
    const float* __restrict__ x, float* __restrict__ out)
{
    __shared__ __align__(16) float xraw[4 + K3_CG * HSZ + 4];
    __shared__ __align__(16) ull cf2_s[K3_CG * TAPS];
    __shared__ __align__(8)  ull mbar_st;

    float* const xh = xraw + 4;

    const int b  = blockIdx.z;
    const int cg = blockIdx.y;
    const int bx = blockIdx.x;
    const int r0 = bx * 8;
    const int tx = threadIdx.x;
    const int ty = threadIdx.y;
    const int tid = ty * 28 + tx;

    const int row = r0 + ty;
    const int col = 2 * tx;

    const unsigned mb = smem_u32(&mbar_st);
    const bool top = (bx == 0), bot = (bx == 6);
    const int nrows = 10 - (top ? 1 : 0) - (bot ? 1 : 0);
    const unsigned tx_bytes = (unsigned)(K3_CG * nrows * WW * 4);

    if (tid == 0)
        asm volatile("mbarrier.init.shared.b64 [%0], 1;" :: "r"(mb) : "memory");
    __syncthreads();
    if (tid == 0)
        asm volatile("mbarrier.arrive.expect_tx.shared.b64 _, [%0], %1;"
                     :: "r"(mb), "r"(tx_bytes) : "memory");
    __syncthreads();

    if (tid < K3_CG) {
        const int gr0    = top ? 0 : (r0 - 1);
        const int dst_rr = top ? 1 : 0;
        const float* src = x + ((size_t)(b * CC + cg * K3_CG + tid) * HW + gr0 * WW);
        const unsigned dst = smem_u32(xh + tid * HSZ + dst_rr * HSTR);
        asm volatile(
            "cp.async.bulk.shared::cta.global.mbarrier::complete_tx::bytes "
            "[%0], [%1], %2, [%3];"
            :: "r"(dst), "l"(src), "r"((unsigned)(nrows * WW * 4)), "r"(mb)
            : "memory");
    }

    if (tid < K3_CG * TAPS) {
        float v = g_cf[(size_t)b * CKK + cg * K3_CG * TAPS + tid];
        cf2_s[tid] = pack2(v, v);
    }

    ull sfr[TAPS];
    {
        const float* sp = g_sf + (size_t)b * TAPS * HW + row * WW + col;
#pragma unroll
        for (int n = 0; n < TAPS; n++)
            sfr[n] = __ldg((const ull*)(sp + n * HW));
    }

    if (top || bot) {
        const int zr = top ? 0 : 9;
        for (int i = tid; i < K3_CG * WW; i += 224) {
            int g = i / WW, j = i - g * WW;
            xh[g * HSZ + zr * HSTR + j] = 0.f;
        }
    }

    __syncthreads();
    {
        unsigned done;
        asm volatile(
            "{\n\t.reg .pred p;\n\t"
            "mbarrier.try_wait.parity.acquire.cta.shared::cta.b64 p, [%1], 0;\n\t"
            "selp.b32 %0, 1, 0, p;\n\t}"
            : "=r"(done) : "r"(mb) : "memory");
        if (!done) {
            asm volatile(
                "{\n\t.reg .pred P1;\n\t"
                "WL_%=:\n\t"
                "mbarrier.try_wait.parity.acquire.cta.shared::cta.b64 P1, [%0], 0, 0x989680;\n\t"
                "@P1 bra.uni WD_%=;\n\t"
                "bra.uni WL_%=;\n\t"
                "WD_%=:\n\t}"
                :: "r"(mb) : "memory");
        }
    }

    const bool eL = (tx == 0);
    const bool eR = (tx == 27);
    const float* hbase = xh + ty * HSTR + col;
    float* po = out + ((size_t)b * CC + cg * K3_CG) * HW + row * WW + col;

#pragma unroll
    for (int g = 0; g < K3_CG; g++) {
        const float* hp = hbase + g * HSZ;
        ull acc = 0ULL;
        const ull* cfp = cf2_s + g * TAPS;

#pragma unroll
        for (int u = 0; u < KK; u++) {
            const float* rp = hp + u * HSTR;
            ull A = *(const ull*)(rp - 2);
            ull Bv = *(const ull*)(rp);
            ull Cv = *(const ull*)(rp + 2);
            float al, ah, bl, bh, cl, ch;
            unpack2(A, al, ah);
            unpack2(Bv, bl, bh);
            unpack2(Cv, cl, ch);
            float xl = eL ? 0.f : ah;
            float xr = eR ? 0.f : cl;
            ull XL = pack2(xl, bl);
            ull XR = pack2(bh, xr);
            acc = fma2(XL, mul2(cfp[u * 3 + 0], sfr[u * 3 + 0]), acc);
            acc = fma2(Bv, mul2(cfp[u * 3 + 1], sfr[u * 3 + 1]), acc);
            acc = fma2(XR, mul2(cfp[u * 3 + 2], sfr[u * 3 + 2]), acc);
        }

        *(ull*)po = acc;
        po += HW;
    }
}

// ---------------------------------------------------------------------------
extern "C" void kernel_launch(void* const* d_in, const int* in_sizes, int n_in,
                              void* d_out, int out_size)
{
    const float* x      = (const float*)d_in[0];
    const float* w1     = (const float*)d_in[1];
    const float* b1     = (const float*)d_in[2];
    const float* w2     = (const float*)d_in[3];
    const float* b2     = (const float*)d_in[4];
    const float* ws     = (const float*)d_in[5];
    const float* bs     = (const float*)d_in[6];
    const float* fn_std = (const float*)d_in[7];
    float* out = (float*)d_out;

    dim3 gA(98 + 16, BB);
    kA_sf_pool<<<gA, 512>>>(x, ws, bs);

    dim3 g2(16, BB);
    k2_mlp_cf<<<g2, 256>>>(w1, b1, w2, b2, fn_std);

    dim3 g3(HH / 8, CC / K3_CG, BB);
    dim3 b3(28, 8);
    k3_ddf<<<g3, b3>>>(x, out);
}